// round 2
// baseline (speedup 1.0000x reference)
#include <cuda_runtime.h>
#include <math.h>

#define NB 16
#define NT 2048
#define ND 512
#define NH 512
#define SIXH 3072
#define MROWS (NB * NT)   // 32768

#define GRID2 128
#define THR2 256
// smem: sh_h 512*16 | sh_wt 512*20 | red 320*9
#define SMEM2_FLOATS (8192 + 10240 + 2880)
#define SMEM2_BYTES (SMEM2_FLOATS * 4)

// ---------------- device scratch (static: no runtime allocation) ----------------
__device__ float g_pi[(size_t)MROWS * SIXH];          // 402 MB: PI = X @ W^T + b
__device__ float g_ht[2][NH * NB];                    // h double buffer, layout [k][b]
__device__ unsigned long long g_bar_count;            // monotonic grid-barrier counter

// ---------------- math helpers (accurate: ~1e-6 rel err) ----------------
__device__ __forceinline__ float sigf(float x) {
    return 1.0f / (1.0f + __expf(-x));
}
__device__ __forceinline__ float tanh_acc(float x) {
    float e = __expf(-2.0f * fabsf(x));
    float t = (1.0f - e) / (1.0f + e);
    return x >= 0.0f ? t : -t;
}

// =====================================================================
// Phase 1: PI[m][n] = sum_k X[m][k] * W[n][k] + bias[n]
// Tiles: 128x128, BK=16, 256 threads, 8x8 microtile. FFMA-bound.
// =====================================================================
#define BK1 16
#define LDA1 132   // padded stride: kills STS bank conflicts (512 % 32 == 0 otherwise)

__global__ void __launch_bounds__(256) gemm_pi_kernel(
    const float* __restrict__ X, const float* __restrict__ W,
    const float* __restrict__ bias)
{
    __shared__ float As[BK1 * LDA1];
    __shared__ float Bs[BK1 * LDA1];

    const int tid = threadIdx.x;
    const int tx = tid & 15, ty = tid >> 4;
    const int n0 = blockIdx.x * 128;
    const int m0 = blockIdx.y * 128;

    const float* Xp = X + (size_t)m0 * ND;
    const float* Wp = W + (size_t)n0 * ND;

    float acc[8][8];
#pragma unroll
    for (int i = 0; i < 8; i++)
#pragma unroll
        for (int j = 0; j < 8; j++) acc[i][j] = 0.0f;

    for (int kc = 0; kc < ND; kc += BK1) {
#pragma unroll
        for (int i = 0; i < 2; i++) {
            int idx4 = tid + 256 * i;
            int row = idx4 >> 2;
            int kq = idx4 & 3;
            float4 va = *(const float4*)(Xp + (size_t)row * ND + kc + kq * 4);
            float4 vb = *(const float4*)(Wp + (size_t)row * ND + kc + kq * 4);
            As[(kq * 4 + 0) * LDA1 + row] = va.x;
            As[(kq * 4 + 1) * LDA1 + row] = va.y;
            As[(kq * 4 + 2) * LDA1 + row] = va.z;
            As[(kq * 4 + 3) * LDA1 + row] = va.w;
            Bs[(kq * 4 + 0) * LDA1 + row] = vb.x;
            Bs[(kq * 4 + 1) * LDA1 + row] = vb.y;
            Bs[(kq * 4 + 2) * LDA1 + row] = vb.z;
            Bs[(kq * 4 + 3) * LDA1 + row] = vb.w;
        }
        __syncthreads();

#pragma unroll
        for (int k = 0; k < BK1; k++) {
            float a[8], b[8];
            *(float4*)&a[0] = *(const float4*)&As[k * LDA1 + ty * 8];
            *(float4*)&a[4] = *(const float4*)&As[k * LDA1 + ty * 8 + 4];
            *(float4*)&b[0] = *(const float4*)&Bs[k * LDA1 + tx * 8];
            *(float4*)&b[4] = *(const float4*)&Bs[k * LDA1 + tx * 8 + 4];
#pragma unroll
            for (int i = 0; i < 8; i++)
#pragma unroll
                for (int j = 0; j < 8; j++)
                    acc[i][j] = fmaf(a[i], b[j], acc[i][j]);
        }
        __syncthreads();
    }

    float bv[8];
#pragma unroll
    for (int j = 0; j < 8; j++) bv[j] = bias[n0 + tx * 8 + j];

#pragma unroll
    for (int i = 0; i < 8; i++) {
        size_t m = (size_t)m0 + ty * 8 + i;
        float* op = g_pi + m * SIXH + n0 + tx * 8;
        float4 r0 = make_float4(acc[i][0] + bv[0], acc[i][1] + bv[1],
                                acc[i][2] + bv[2], acc[i][3] + bv[3]);
        float4 r1 = make_float4(acc[i][4] + bv[4], acc[i][5] + bv[5],
                                acc[i][6] + bv[6], acc[i][7] + bv[7]);
        *(float4*)op = r0;
        *(float4*)(op + 4) = r1;
    }
}

// =====================================================================
// Grid barrier: monotonic counter, safe across graph replays (never resets).
// All 128 CTAs are co-resident (grid <= SM count), so spinning is safe.
// =====================================================================
__device__ __forceinline__ void grid_barrier() {
    __syncthreads();
    if (threadIdx.x == 0) {
        __threadfence();
        unsigned long long arrive = atomicAdd(&g_bar_count, 1ULL);
        unsigned long long target = (arrive / GRID2 + 1ULL) * GRID2;
        if (arrive + 1ULL != target) {
            volatile unsigned long long* p =
                (volatile unsigned long long*)&g_bar_count;
            while (*p < target) { }
        }
        __threadfence();
    }
    __syncthreads();
}

// =====================================================================
// Phase 2: persistent recurrence kernel.
// CTA owns 4 output channels jo = cta*4 .. +3, i.e. 20 W rows
// (5 gates x 4 channels), held in SMEM for all 2048 steps.
// Per step: stage h (transposed [k][b]) into SMEM; 8 warps K-split (64 each);
// each lane computes a 2b x 5jr register microtile; SMEM tree-reduce;
// 64 combine threads (b,joff) do gate math, keep c in registers,
// write out + next h; grid barrier.
// =====================================================================
__global__ void __launch_bounds__(THR2, 1) lstm_rec_kernel(
    const float* __restrict__ W, const float* __restrict__ bias,
    const int* __restrict__ lengths, float* __restrict__ out)
{
    extern __shared__ float smem[];
    float* sh_h  = smem;                  // [512][16]  (k-major)
    float* sh_wt = smem + 8192;           // [512][20]  (k-major, jr inner)
    float* red   = smem + 8192 + 10240;   // [320][9]   (stride-9 pad)

    const int tid = threadIdx.x;
    const int cta = blockIdx.x;
    const int jo_base = cta * 4;

    // --- load persistent W slice: jr = gate*4 + joff -> row gate*512 + jo ---
    for (int idx = tid; idx < 20 * 512; idx += THR2) {
        int jr = idx >> 9;
        int k = idx & 511;
        int j = (jr >> 2) * NH + jo_base + (jr & 3);
        sh_wt[k * 20 + jr] = W[(size_t)j * ND + k];
    }

    // --- combine-thread persistent state ---
    int b_c = 0, jo_c = 0, len_c = 0;
    float bias5[5] = {0, 0, 0, 0, 0};
    float c_reg = 0.0f;
    if (tid < 64) {
        b_c = tid >> 2;
        jo_c = jo_base + (tid & 3);
#pragma unroll
        for (int g = 0; g < 5; g++) bias5[g] = bias[g * NH + jo_c];
        len_c = lengths[b_c];
    }

    // --- zero h buffer 0 (fresh every launch -> deterministic) ---
    if (tid < 64) {
        g_ht[0][cta * 64 + tid] = 0.0f;
        __threadfence();
    }
    grid_barrier();

    const int warp = tid >> 5, lane = tid & 31;
    const int bg = lane & 7;   // b pair {2bg, 2bg+1}
    const int jg = lane >> 3;  // jr group {5jg .. 5jg+4}
    const float* hp0 = sh_h + (warp * 64) * 16 + 2 * bg;
    const float* wp0 = sh_wt + (warp * 64) * 20 + jg * 5;

    for (int t = 0; t < NT; t++) {
        const float* hbuf = g_ht[t & 1];
        float* hnext = g_ht[(t & 1) ^ 1];

        // stage h (already transposed [k][b]) -> straight coalesced copy
#pragma unroll
        for (int i = 0; i < 8; i++) {
            int off = tid * 4 + i * 1024;
            *(float4*)&sh_h[off] = *(const float4*)&hbuf[off];
        }

        // prefetch PI early: DRAM latency hides behind the compute loop
        float pi5[5] = {0, 0, 0, 0, 0}, pi6 = 0.0f;
        if (tid < 64) {
            const float* pr = g_pi + ((size_t)b_c * NT + t) * SIXH + jo_c;
#pragma unroll
            for (int g = 0; g < 5; g++) pi5[g] = pr[g * NH];
            pi6 = pr[5 * NH];
        }
        __syncthreads();

        // --- K-split partial GEMM: 2b x 5jr per lane over 64 k ---
        float acc[2][5];
#pragma unroll
        for (int bb = 0; bb < 2; bb++)
#pragma unroll
            for (int u = 0; u < 5; u++) acc[bb][u] = 0.0f;

        {
            const float* hp = hp0;
            const float* wp = wp0;
#pragma unroll 8
            for (int kk = 0; kk < 64; kk++) {
                float2 hv = *(const float2*)hp;
                float w0 = wp[0], w1 = wp[1], w2 = wp[2], w3 = wp[3], w4 = wp[4];
                acc[0][0] = fmaf(hv.x, w0, acc[0][0]);
                acc[0][1] = fmaf(hv.x, w1, acc[0][1]);
                acc[0][2] = fmaf(hv.x, w2, acc[0][2]);
                acc[0][3] = fmaf(hv.x, w3, acc[0][3]);
                acc[0][4] = fmaf(hv.x, w4, acc[0][4]);
                acc[1][0] = fmaf(hv.y, w0, acc[1][0]);
                acc[1][1] = fmaf(hv.y, w1, acc[1][1]);
                acc[1][2] = fmaf(hv.y, w2, acc[1][2]);
                acc[1][3] = fmaf(hv.y, w3, acc[1][3]);
                acc[1][4] = fmaf(hv.y, w4, acc[1][4]);
                hp += 16;
                wp += 20;
            }
        }

#pragma unroll
        for (int bb = 0; bb < 2; bb++)
#pragma unroll
            for (int u = 0; u < 5; u++)
                red[((2 * bg + bb) * 20 + jg * 5 + u) * 9 + warp] = acc[bb][u];
        __syncthreads();

        // --- reduce across 8 warps + gate math (64 threads) ---
        if (tid < 64) {
            float gv[5];
#pragma unroll
            for (int g = 0; g < 5; g++) {
                int o = b_c * 20 + g * 4 + (tid & 3);
                const float* rp = red + o * 9;
                float s = ((rp[0] + rp[1]) + (rp[2] + rp[3])) +
                          ((rp[4] + rp[5]) + (rp[6] + rp[7]));
                gv[g] = s + bias5[g] + pi5[g];
            }
            float ig = sigf(gv[0]);
            float fg = sigf(gv[1]);
            float mi = tanh_acc(gv[2]);
            float og = sigf(gv[3]);
            float hwg = sigf(gv[4]);
            float mem = fmaf(ig, mi, fg * c_reg);
            float o_ = og * tanh_acc(mem);
            o_ = fmaf(hwg, o_ - pi6, pi6);  // hw*o + (1-hw)*pi6
            if (t >= len_c) { o_ = 0.0f; mem = 0.0f; }
            c_reg = mem;

            out[((size_t)b_c * NT + t) * NH + jo_c] = o_;
            hnext[jo_c * 16 + b_c] = o_;   // transposed for next step's copy
            __threadfence();
        }
        grid_barrier();
    }
}

// =====================================================================
// launch
// =====================================================================
extern "C" void kernel_launch(void* const* d_in, const int* in_sizes, int n_in,
                              void* d_out, int out_size) {
    const float* x = (const float*)d_in[0];
    const int* lengths = (const int*)d_in[1];
    const float* W = (const float*)d_in[2];
    const float* bias = (const float*)d_in[3];
    float* out = (float*)d_out;

    // opt-in to >48KB dynamic smem once (first call = uncaptured correctness run)
    static bool attr_done = false;
    if (!attr_done) {
        cudaFuncSetAttribute(lstm_rec_kernel,
                             cudaFuncAttributeMaxDynamicSharedMemorySize,
                             SMEM2_BYTES);
        attr_done = true;
    }

    dim3 g1(SIXH / 128, MROWS / 128);  // (24, 256)
    gemm_pi_kernel<<<g1, 256>>>(x, W, bias);
    lstm_rec_kernel<<<GRID2, THR2, SMEM2_BYTES>>>(W, bias, lengths, out);
}

// round 3
// speedup vs baseline: 1.0765x; 1.0765x over previous
#include <cuda_runtime.h>
#include <math.h>

#define NB 16
#define NT 2048
#define ND 512
#define NH 512
#define SIXH 3072
#define MROWS (NB * NT)   // 32768

#define GRID2 128
#define THR2 256
// smem: sh_h 512*16 | sh_wt 512*32 (padded j-groups) | red 320*9
#define SMEM2_FLOATS (8192 + 16384 + 2880)
#define SMEM2_BYTES (SMEM2_FLOATS * 4)

typedef unsigned long long u64;

// ---------------- device scratch (static: no runtime allocation) ----------------
__device__ float g_pi[(size_t)MROWS * SIXH];          // 402 MB: PI = X @ W^T + b
__device__ float g_ht[2][NH * NB];                    // h double buffer, layout [k][b]
__device__ unsigned long long g_bar_count;            // monotonic grid-barrier counter

// ---------------- packed f32x2 helpers (SASS FFMA2 — exact fp32 numerics) -------
__device__ __forceinline__ u64 pack2(float lo, float hi) {
    u64 r;
    asm("mov.b64 %0, {%1, %2};" : "=l"(r) : "f"(lo), "f"(hi));
    return r;
}
__device__ __forceinline__ void unpack2(u64 v, float& lo, float& hi) {
    asm("mov.b64 {%0, %1}, %2;" : "=f"(lo), "=f"(hi) : "l"(v));
}
__device__ __forceinline__ void fma2(u64& d, u64 a, u64 b) {
    asm("fma.rn.f32x2 %0, %1, %2, %0;" : "+l"(d) : "l"(a), "l"(b));
}

// ---------------- math helpers (accurate: ~1e-6 rel err) ----------------
__device__ __forceinline__ float sigf(float x) {
    return 1.0f / (1.0f + __expf(-x));
}
__device__ __forceinline__ float tanh_acc(float x) {
    float e = __expf(-2.0f * fabsf(x));
    float t = (1.0f - e) / (1.0f + e);
    return x >= 0.0f ? t : -t;
}

// =====================================================================
// Phase 1: PI[m][n] = sum_k X[m][k] * W[n][k] + bias[n]
// Tiles: 128x128, BK=16, 256 threads, 8x8 microtile done as 8x4 FFMA2.
// =====================================================================
#define BK1 16
#define LDA1 132   // padded stride (528B = 33*16 -> 16B-aligned vector rows)

__global__ void __launch_bounds__(256) gemm_pi_kernel(
    const float* __restrict__ X, const float* __restrict__ W,
    const float* __restrict__ bias)
{
    __shared__ float As[BK1 * LDA1];
    __shared__ float Bs[BK1 * LDA1];

    const int tid = threadIdx.x;
    const int tx = tid & 15, ty = tid >> 4;
    const int n0 = blockIdx.x * 128;
    const int m0 = blockIdx.y * 128;

    const float* Xp = X + (size_t)m0 * ND;
    const float* Wp = W + (size_t)n0 * ND;

    u64 accP[8][4];
#pragma unroll
    for (int i = 0; i < 8; i++)
#pragma unroll
        for (int j = 0; j < 4; j++) accP[i][j] = 0ULL;

    for (int kc = 0; kc < ND; kc += BK1) {
#pragma unroll
        for (int i = 0; i < 2; i++) {
            int idx4 = tid + 256 * i;
            int row = idx4 >> 2;
            int kq = idx4 & 3;
            float4 va = *(const float4*)(Xp + (size_t)row * ND + kc + kq * 4);
            float4 vb = *(const float4*)(Wp + (size_t)row * ND + kc + kq * 4);
            As[(kq * 4 + 0) * LDA1 + row] = va.x;
            As[(kq * 4 + 1) * LDA1 + row] = va.y;
            As[(kq * 4 + 2) * LDA1 + row] = va.z;
            As[(kq * 4 + 3) * LDA1 + row] = va.w;
            Bs[(kq * 4 + 0) * LDA1 + row] = vb.x;
            Bs[(kq * 4 + 1) * LDA1 + row] = vb.y;
            Bs[(kq * 4 + 2) * LDA1 + row] = vb.z;
            Bs[(kq * 4 + 3) * LDA1 + row] = vb.w;
        }
        __syncthreads();

#pragma unroll
        for (int k = 0; k < BK1; k++) {
            float a[8];
            *(float4*)&a[0] = *(const float4*)&As[k * LDA1 + ty * 8];
            *(float4*)&a[4] = *(const float4*)&As[k * LDA1 + ty * 8 + 4];
            ulonglong2 b01 = *(const ulonglong2*)&Bs[k * LDA1 + tx * 8];
            ulonglong2 b23 = *(const ulonglong2*)&Bs[k * LDA1 + tx * 8 + 4];
#pragma unroll
            for (int i = 0; i < 8; i++) {
                u64 ad = pack2(a[i], a[i]);
                fma2(accP[i][0], b01.x, ad);
                fma2(accP[i][1], b01.y, ad);
                fma2(accP[i][2], b23.x, ad);
                fma2(accP[i][3], b23.y, ad);
            }
        }
        __syncthreads();
    }

    float bv[8];
#pragma unroll
    for (int j = 0; j < 8; j++) bv[j] = bias[n0 + tx * 8 + j];

#pragma unroll
    for (int i = 0; i < 8; i++) {
        float c[8];
#pragma unroll
        for (int jp = 0; jp < 4; jp++)
            unpack2(accP[i][jp], c[2 * jp], c[2 * jp + 1]);
        size_t m = (size_t)m0 + ty * 8 + i;
        float* op = g_pi + m * SIXH + n0 + tx * 8;
        float4 r0 = make_float4(c[0] + bv[0], c[1] + bv[1],
                                c[2] + bv[2], c[3] + bv[3]);
        float4 r1 = make_float4(c[4] + bv[4], c[5] + bv[5],
                                c[6] + bv[6], c[7] + bv[7]);
        *(float4*)op = r0;
        *(float4*)(op + 4) = r1;
    }
}

// =====================================================================
// Grid barrier: monotonic counter, safe across graph replays (never resets).
// All 128 CTAs are co-resident (grid <= SM count, 1 CTA/SM), spinning safe.
// =====================================================================
__device__ __forceinline__ void grid_barrier() {
    __syncthreads();
    if (threadIdx.x == 0) {
        __threadfence();
        unsigned long long arrive = atomicAdd(&g_bar_count, 1ULL);
        unsigned long long target = (arrive / GRID2 + 1ULL) * GRID2;
        if (arrive + 1ULL != target) {
            volatile unsigned long long* p =
                (volatile unsigned long long*)&g_bar_count;
            while (*p < target) { }
        }
        __threadfence();
    }
    __syncthreads();
}

// =====================================================================
// Phase 2: persistent recurrence kernel.
// CTA owns 4 output channels (jg=0..3), 5 gates each -> 20 W rows held in
// SMEM as [k][32] (gate u at jg*8+u, padded so {w0,w1},{w2,w3} are aligned
// 64-bit pairs). 8 warps K-split (64 k each); lane = (bg,jg) computes a
// 2b x 5gate microtile with packed FFMA2; SMEM tree-reduce; 64 combine
// threads do gate math with c in registers; grid barrier per step.
// =====================================================================
__global__ void __launch_bounds__(THR2, 1) lstm_rec_kernel(
    const float* __restrict__ W, const float* __restrict__ bias,
    const int* __restrict__ lengths, float* __restrict__ out)
{
    extern __shared__ float smem[];
    float* sh_h  = smem;                  // [512][16]  (k-major)
    float* sh_wt = smem + 8192;           // [512][32]  (k-major, jg*8+u, padded)
    float* red   = smem + 8192 + 16384;   // [320][9]   (stride-9 pad)

    const int tid = threadIdx.x;
    const int cta = blockIdx.x;
    const int jo_base = cta * 4;

    // --- load persistent W slice: sh_wt[k*32 + jg*8 + u] = W[u*NH+jo_base+jg][k]
    for (int p = tid; p < 20 * 512; p += THR2) {
        int k = p & 511;
        int r = p >> 9;          // 0..19
        int u = r >> 2;          // gate
        int jg = r & 3;          // channel offset
        sh_wt[k * 32 + jg * 8 + u] =
            W[(size_t)(u * NH + jo_base + jg) * ND + k];
    }

    // --- combine-thread persistent state ---
    int b_c = 0, jo_c = 0, len_c = 0;
    float bias5[5] = {0, 0, 0, 0, 0};
    float c_reg = 0.0f;
    if (tid < 64) {
        b_c = tid >> 2;
        jo_c = jo_base + (tid & 3);
#pragma unroll
        for (int g = 0; g < 5; g++) bias5[g] = bias[g * NH + jo_c];
        len_c = lengths[b_c];
    }

    // --- zero h buffer 0 (fresh every launch -> deterministic) ---
    if (tid < 64) g_ht[0][cta * 64 + tid] = 0.0f;
    grid_barrier();

    const int warp = tid >> 5, lane = tid & 31;
    const int bg = lane & 7;   // batch pair {2bg, 2bg+1}
    const int jg = lane >> 3;  // channel offset within CTA
    const u64*   hp0 = (const u64*)(sh_h + (size_t)warp * 64 * 16 + 2 * bg);
    const float* wp0 = sh_wt + (size_t)warp * 64 * 32 + jg * 8;

    for (int t = 0; t < NT; t++) {
        const float* hbuf = g_ht[t & 1];
        float* hnext = g_ht[(t & 1) ^ 1];

        // prefetch PI early (DRAM latency hides behind staging + gemm)
        float pi5[5] = {0, 0, 0, 0, 0}, pi6 = 0.0f;
        if (tid < 64) {
            const float* pr = g_pi + ((size_t)b_c * NT + t) * SIXH + jo_c;
#pragma unroll
            for (int g = 0; g < 5; g++) pi5[g] = pr[g * NH];
            pi6 = pr[5 * NH];
        }

        // stage h (already transposed [k][b]) -> straight coalesced copy
#pragma unroll
        for (int i = 0; i < 8; i++) {
            int off = tid * 4 + i * 1024;
            *(float4*)&sh_h[off] = *(const float4*)&hbuf[off];
        }
        __syncthreads();

        // --- K-split packed-FFMA2 partial GEMM: 2b x 5gate per lane, 64 k ---
        u64 a01_b0 = 0, a23_b0 = 0, a01_b1 = 0, a23_b1 = 0, a4 = 0;
        {
            const u64* hp = hp0;
            const float* wp = wp0;
#pragma unroll 8
            for (int kk = 0; kk < 64; kk++) {
                u64 hd = *hp;                                // {h_b0, h_b1}
                ulonglong2 wv = *(const ulonglong2*)wp;      // {w0,w1},{w2,w3}
                float w4 = wp[4];
                float h0, h1;
                unpack2(hd, h0, h1);
                u64 h00 = pack2(h0, h0);
                u64 h11 = pack2(h1, h1);
                u64 w44 = pack2(w4, w4);
                fma2(a01_b0, wv.x, h00);
                fma2(a23_b0, wv.y, h00);
                fma2(a01_b1, wv.x, h11);
                fma2(a23_b1, wv.y, h11);
                fma2(a4, hd, w44);                           // {b0,b1} x w4
                hp += 8;
                wp += 32;
            }
        }

        // unpack and write partials: row = b*20 + gate*4 + jg
        {
            float v0, v1, v2, v3, v4b0, v4b1, u0, u1, u2, u3;
            unpack2(a01_b0, v0, v1);
            unpack2(a23_b0, v2, v3);
            unpack2(a01_b1, u0, u1);
            unpack2(a23_b1, u2, u3);
            unpack2(a4, v4b0, v4b1);
            int rb0 = (2 * bg) * 20 + jg;
            int rb1 = (2 * bg + 1) * 20 + jg;
            red[(rb0 + 0 * 4) * 9 + warp] = v0;
            red[(rb0 + 1 * 4) * 9 + warp] = v1;
            red[(rb0 + 2 * 4) * 9 + warp] = v2;
            red[(rb0 + 3 * 4) * 9 + warp] = v3;
            red[(rb0 + 4 * 4) * 9 + warp] = v4b0;
            red[(rb1 + 0 * 4) * 9 + warp] = u0;
            red[(rb1 + 1 * 4) * 9 + warp] = u1;
            red[(rb1 + 2 * 4) * 9 + warp] = u2;
            red[(rb1 + 3 * 4) * 9 + warp] = u3;
            red[(rb1 + 4 * 4) * 9 + warp] = v4b1;
        }
        __syncthreads();

        // --- reduce across 8 warps + gate math (64 threads) ---
        if (tid < 64) {
            float gv[5];
#pragma unroll
            for (int g = 0; g < 5; g++) {
                int o = b_c * 20 + g * 4 + (tid & 3);
                const float* rp = red + o * 9;
                float s = ((rp[0] + rp[1]) + (rp[2] + rp[3])) +
                          ((rp[4] + rp[5]) + (rp[6] + rp[7]));
                gv[g] = s + bias5[g] + pi5[g];
            }
            float ig = sigf(gv[0]);
            float fg = sigf(gv[1]);
            float mi = tanh_acc(gv[2]);
            float og = sigf(gv[3]);
            float hwg = sigf(gv[4]);
            float mem = fmaf(ig, mi, fg * c_reg);
            float o_ = og * tanh_acc(mem);
            o_ = fmaf(hwg, o_ - pi6, pi6);  // hw*o + (1-hw)*pi6
            if (t >= len_c) { o_ = 0.0f; mem = 0.0f; }
            c_reg = mem;

            out[((size_t)b_c * NT + t) * NH + jo_c] = o_;
            hnext[jo_c * 16 + b_c] = o_;   // transposed for next step's copy
        }
        grid_barrier();
    }
}

// =====================================================================
// launch
// =====================================================================
extern "C" void kernel_launch(void* const* d_in, const int* in_sizes, int n_in,
                              void* d_out, int out_size) {
    const float* x = (const float*)d_in[0];
    const int* lengths = (const int*)d_in[1];
    const float* W = (const float*)d_in[2];
    const float* bias = (const float*)d_in[3];
    float* out = (float*)d_out;

    static bool attr_done = false;
    if (!attr_done) {
        cudaFuncSetAttribute(lstm_rec_kernel,
                             cudaFuncAttributeMaxDynamicSharedMemorySize,
                             SMEM2_BYTES);
        attr_done = true;
    }

    dim3 g1(SIXH / 128, MROWS / 128);  // (24, 256)
    gemm_pi_kernel<<<g1, 256>>>(x, W, bias);
    lstm_rec_kernel<<<GRID2, THR2, SMEM2_BYTES>>>(W, bias, lengths, out);
}